// round 10
// baseline (speedup 1.0000x reference)
#include <cuda_runtime.h>
#include <math.h>

#define NTOK 32768
#define NB 4

typedef unsigned long long u64;

__device__ __forceinline__ u64 pk(float lo, float hi) {
    u64 r; asm("mov.b64 %0,{%1,%2};" : "=l"(r) : "f"(lo), "f"(hi)); return r;
}
__device__ __forceinline__ u64 dupf(float v) {
    u64 r; asm("mov.b64 %0,{%1,%1};" : "=l"(r) : "f"(v)); return r;
}
__device__ __forceinline__ float2 up(u64 v) {
    float2 f; asm("mov.b64 {%0,%1},%2;" : "=f"(f.x), "=f"(f.y) : "l"(v)); return f;
}
__device__ __forceinline__ void ffma2(u64& d, u64 a, u64 b) {
    asm("fma.rn.f32x2 %0,%1,%2,%0;" : "+l"(d) : "l"(a), "l"(b));
}
__device__ __forceinline__ float hadd(u64 v) { float2 f = up(v); return f.x + f.y; }

// ------------------------- scratch (__device__ globals) -------------------------
__device__ float g_qkvvT[(size_t)NB * 512 * NTOK];   // [b][j][n]  j: 0q 128k 256vCA 384vSA
__device__ float g_fconv[(size_t)NB * 512 * NTOK];   // [b][d*16+o][n]
__device__ float g_outconv[(size_t)NB * 128 * NTOK]; // [b][oc][n]
__device__ float g_SA[(size_t)NB * NTOK * 128];      // scrambled x_SA rows
__device__ float g_xCA[(size_t)NB * NTOK * 128];     // [b][n][c]
__device__ float g_gpart[16 * 64 * 1088];
__device__ float g_ppart[16 * 16 * 2 * 2048];
__device__ float g_nq[512];
__device__ float g_attnCA[16 * 1024];
__device__ float g_kps[16 * 2048];
__device__ float g_vproj[16 * 2048];

// ------------------------- K1: qkvvT = Wq @ x  (R5 version, measured good) ----
__global__ __launch_bounds__(256) void k1_qkvv(const float* __restrict__ x,
                                               const float* __restrict__ Wq) {
    __shared__ float xs[32 * 128];
    __shared__ u64 ws2[32 * 64];
    const int t = threadIdx.x;
    const int n0 = blockIdx.x * 128;
    const int j0 = blockIdx.y * 64;
    const int b  = blockIdx.z;
    const int nt = t & 31;   // token group: tokens nt*4 .. nt*4+3
    const int jt = t >> 5;   // 0..7, 8 j each
    u64 acc0[8], acc1[8];
#pragma unroll
    for (int j = 0; j < 8; j++) { acc0[j] = 0ull; acc1[j] = 0ull; }

    for (int kc = 0; kc < 4; kc++) {
        const int k0 = kc * 32;
#pragma unroll
        for (int r = 0; r < 16; r++) {
            int e = t + r * 256;
            int kk = e >> 7, nl = e & 127;
            xs[e] = x[((size_t)(b * 128 + k0 + kk)) * NTOK + n0 + nl];
        }
#pragma unroll
        for (int r = 0; r < 8; r++) {
            int e = t + r * 256;
            int kk = e >> 6, j = e & 63;
            ws2[kk * 64 + j] = dupf(Wq[(j0 + j) * 128 + k0 + kk]);
        }
        __syncthreads();
#pragma unroll
        for (int kk = 0; kk < 32; kk++) {
            float4 xv = *(const float4*)&xs[kk * 128 + nt * 4];
            u64 x0 = pk(xv.x, xv.y), x1 = pk(xv.z, xv.w);
            const u64* wrow = &ws2[kk * 64 + jt * 8];
#pragma unroll
            for (int jj = 0; jj < 8; jj++) {
                u64 w = wrow[jj];
                ffma2(acc0[jj], x0, w);
                ffma2(acc1[jj], x1, w);
            }
        }
        __syncthreads();
    }
#pragma unroll
    for (int jj = 0; jj < 8; jj++) {
        float2 a0 = up(acc0[jj]), a1 = up(acc1[jj]);
        size_t rb = ((size_t)(b * 512 + j0 + jt * 8 + jj)) * NTOK + n0 + nt * 4;
        *(float4*)&g_qkvvT[rb] = make_float4(a0.x, a0.y, a1.x, a1.y);
    }
}

// ------------------------- K2: Gram partials + sq-sums (packed over tt) -------
__global__ __launch_bounds__(256) void k2_gram() {
    __shared__ float qs[32 * 66];
    __shared__ float ks[32 * 66];
    const int s = blockIdx.x;
    const int h = blockIdx.y, b = blockIdx.z;
    const int bh = b * 4 + h;
    const int t = threadIdx.x;
    const int d = t >> 3, e0 = (t & 7) * 4;
    u64 acc2[4] = {0ull, 0ull, 0ull, 0ull};
    u64 nacc2 = 0ull;
    for (int sub = 0; sub < 8; sub++) {
        const int n0 = s * 512 + sub * 64;
#pragma unroll
        for (int r = 0; r < 8; r++) {
            int e = t + r * 256;
            int dd = e >> 6, tt = e & 63;
            qs[dd * 66 + tt] = g_qkvvT[((size_t)(b * 512 + h * 32 + dd)) * NTOK + n0 + tt];
            ks[dd * 66 + tt] = g_qkvvT[((size_t)(b * 512 + 128 + h * 32 + dd)) * NTOK + n0 + tt];
        }
        __syncthreads();
#pragma unroll 8
        for (int tt = 0; tt < 64; tt += 2) {
            u64 qp = *(const u64*)&qs[d * 66 + tt];
#pragma unroll
            for (int j = 0; j < 4; j++)
                ffma2(acc2[j], qp, *(const u64*)&ks[(e0 + j) * 66 + tt]);
        }
        if (t < 32) {
#pragma unroll 8
            for (int tt = 0; tt < 64; tt += 2) {
                u64 v = *(const u64*)&qs[t * 66 + tt];
                ffma2(nacc2, v, v);
            }
        } else if (t < 64) {
#pragma unroll 8
            for (int tt = 0; tt < 64; tt += 2) {
                u64 v = *(const u64*)&ks[(t - 32) * 66 + tt];
                ffma2(nacc2, v, v);
            }
        }
        __syncthreads();
    }
    float* part = &g_gpart[(bh * 64 + s) * 1088];
#pragma unroll
    for (int j = 0; j < 4; j++) part[d * 32 + e0 + j] = hadd(acc2[j]);
    if (t < 64) part[1024 + t] = hadd(nacc2);
}

// ------------------------- K3: reduce Gram -> norms, attn_CA ------------------
__global__ __launch_bounds__(256) void k3_red(const float* __restrict__ temperature) {
    __shared__ float Gs[32 * 33];
    __shared__ float nqs[32], nks[32];
    const int bh = blockIdx.x;
    const int h = bh & 3;
    const int t = threadIdx.x;
    for (int i = t; i < 1024; i += 256) {
        float s = 0.f;
        for (int c = 0; c < 64; c++) s += g_gpart[(bh * 64 + c) * 1088 + i];
        Gs[(i >> 5) * 33 + (i & 31)] = s;
    }
    if (t < 64) {
        float s = 0.f;
        for (int c = 0; c < 64; c++) s += g_gpart[(bh * 64 + c) * 1088 + 1024 + t];
        float nv = fmaxf(sqrtf(s), 1e-12f);
        if (t < 32) { nqs[t] = nv; g_nq[bh * 32 + t] = nv; }
        else        { nks[t - 32] = nv; }
    }
    __syncthreads();
    if (t < 32) {
        const int d = t;
        const float temp = temperature[h];
        float v[32];
        float m = -3.4e38f;
        float inq = 1.f / nqs[d];
#pragma unroll
        for (int e = 0; e < 32; e++) {
            v[e] = Gs[d * 33 + e] * temp * inq / nks[e];
            m = fmaxf(m, v[e]);
        }
        float ssum = 0.f;
#pragma unroll
        for (int e = 0; e < 32; e++) { v[e] = expf(v[e] - m); ssum += v[e]; }
        float inv = 1.f / ssum;
#pragma unroll
        for (int e = 0; e < 32; e++) g_attnCA[bh * 1024 + d * 32 + e] = v[e] * inv;
    }
}

// ---------------- K4: E/F projections (mat in grid.z, 4d x 2p / thread) -------
__global__ __launch_bounds__(256) void k4_proj(const float* __restrict__ WE) {
    __shared__ float kt[32 * 66];
    __shared__ float wt[64 * 66];
    const int chunk = blockIdx.x;  // 0..15 (2048 tokens)
    const int bh = blockIdx.y;
    const int mat = blockIdx.z;    // 0: k, 1: v
    const int b = bh >> 2, h = bh & 3;
    const int t = threadIdx.x;
    const int pg = t & 31;         // p: pg, pg+32
    const int dg = t >> 5;         // d = dg*4 .. +3
    const int rowbase = (mat ? 384 : 128) + h * 32;
    u64 a0[4], a1[4];
#pragma unroll
    for (int j = 0; j < 4; j++) { a0[j] = 0ull; a1[j] = 0ull; }
    for (int sub = 0; sub < 32; sub++) {
        const int n0 = chunk * 2048 + sub * 64;
#pragma unroll
        for (int r = 0; r < 8; r++) {
            int e = t + r * 256;
            int dd = e >> 6, tt = e & 63;
            kt[dd * 66 + tt] = g_qkvvT[((size_t)(b * 512 + rowbase + dd)) * NTOK + n0 + tt];
        }
#pragma unroll
        for (int r = 0; r < 16; r++) {
            int e = t + r * 256;
            int pp = e >> 6, tt = e & 63;
            wt[pp * 66 + tt] = WE[(size_t)pp * NTOK + n0 + tt];
        }
        __syncthreads();
#pragma unroll 8
        for (int tt = 0; tt < 64; tt += 2) {
            u64 w0 = *(const u64*)&wt[pg * 66 + tt];
            u64 w1 = *(const u64*)&wt[(pg + 32) * 66 + tt];
#pragma unroll
            for (int j = 0; j < 4; j++) {
                u64 kp = *(const u64*)&kt[(dg * 4 + j) * 66 + tt];
                ffma2(a0[j], kp, w0);
                ffma2(a1[j], kp, w1);
            }
        }
        __syncthreads();
    }
    float* pko = &g_ppart[((size_t)(bh * 16 + chunk) * 2) * 2048] + mat * 2048;
#pragma unroll
    for (int j = 0; j < 4; j++) {
        pko[(dg * 4 + j) * 64 + pg] = hadd(a0[j]);
        pko[(dg * 4 + j) * 64 + pg + 32] = hadd(a1[j]);
    }
}

// ------------------------- K5: reduce projections, fold scales ----------------
__global__ __launch_bounds__(256) void k5_projred(const float* __restrict__ bE,
                                                  const float* __restrict__ temp2) {
    const int bh = blockIdx.x;
    const int h = bh & 3;
    const int t = threadIdx.x;
    const float t2 = temp2[h];
    for (int idx = t; idx < 2048; idx += 256) {
        const int d = idx >> 6, p = idx & 63;
        float sk = 0.f, sv = 0.f;
        for (int c = 0; c < 16; c++) {
            const float* base = &g_ppart[((size_t)(bh * 16 + c) * 2) * 2048];
            sk += base[idx];
            sv += base[2048 + idx];
        }
        const float be = bE[p];
        g_kps[bh * 2048 + idx] = (sk + be) * t2 / g_nq[bh * 32 + d];
        g_vproj[bh * 2048 + idx] = sv + be;
    }
}

// ------------- K6: 1x1 conv (fc), packed, d split over grid.z -----------------
__global__ __launch_bounds__(256) void k6_fc(const float* __restrict__ Wfc,
                                             const float* __restrict__ bfc) {
    __shared__ u64 wf2[256];
    __shared__ float bf[16];
    const int t = threadIdx.x;
    const int b = blockIdx.y;
    const int d0 = blockIdx.z * 8;
    const int n = blockIdx.x * 1024 + t * 4;
    wf2[t] = dupf(Wfc[t]);
    if (t < 16) bf[t] = bfc[t];
    __syncthreads();
    for (int dd = 0; dd < 8; dd++) {
        const int d = d0 + dd;
        u64 oa[16], ob[16];
#pragma unroll
        for (int o = 0; o < 16; o++) { oa[o] = dupf(bf[o]); ob[o] = oa[o]; }
#pragma unroll
        for (int i = 0; i < 16; i++) {
            float4 in4 = *(const float4*)&g_qkvvT[((size_t)(b * 512 + i * 32 + d)) * NTOK + n];
            u64 xa = pk(in4.x, in4.y), xb = pk(in4.z, in4.w);
#pragma unroll
            for (int o = 0; o < 16; o++) {
                u64 w = wf2[o * 16 + i];
                ffma2(oa[o], xa, w);
                ffma2(ob[o], xb, w);
            }
        }
#pragma unroll
        for (int o = 0; o < 16; o++) {
            float2 a = up(oa[o]), c = up(ob[o]);
            *(float4*)&g_fconv[((size_t)(b * 512 + d * 16 + o)) * NTOK + n] =
                make_float4(a.x, a.y, c.x, c.y);
        }
    }
}

// ------------------------- K7: grouped 3x3x3 conv (packed over d3 pairs) ------
__global__ __launch_bounds__(256) void k7_conv(const float* __restrict__ Wd,
                                               const float* __restrict__ bd) {
    __shared__ float s[2 * 6 * 18 * 34];
    __shared__ float wblk[4 * 16 * 27];
    const int t = threadIdx.x;
    const int tile = blockIdx.x;
    const int g = blockIdx.y;
    const int b = blockIdx.z;
    const int h0 = (tile >> 1) * 4;
    const int w0 = (tile & 1) * 16;
    for (int i = t; i < 1728; i += 256) {
        int ol = i / 432, rem = i % 432;
        wblk[i] = Wd[(g * 4 + ol) * 432 + rem];
    }
    const int lw = t & 15, lh = (t >> 4) & 3, ol = t >> 6;
    const int oc = g * 4 + ol;
    u64 acc2[16];
#pragma unroll
    for (int j = 0; j < 16; j++) acc2[j] = 0ull;

    for (int ci = 0; ci < 8; ci++) {
        __syncthreads();
        if (t < 216) {
            const int l = t / 108, rem = t % 108;
            const int hh = rem / 18, ww = rem % 18;
            const int h_s = h0 - 1 + hh, w_s = w0 - 1 + ww;
            float* line = &s[((l * 6 + hh) * 18 + ww) * 34];
            if (h_s >= 0 && h_s < 32 && w_s >= 0 && w_s < 32) {
                const float* src = &g_fconv[((size_t)(b * 512 + g * 16 + ci * 2 + l)) * NTOK +
                                            h_s * 1024 + w_s * 32];
                line[0] = 0.f;
                line[33] = 0.f;
#pragma unroll
                for (int k = 0; k < 8; k++) {
                    float4 v = *(const float4*)&src[k * 4];
                    line[1 + k * 4] = v.x; line[2 + k * 4] = v.y;
                    line[3 + k * 4] = v.z; line[4 + k * 4] = v.w;
                }
            } else {
#pragma unroll
                for (int k = 0; k < 34; k++) line[k] = 0.f;
            }
        }
        __syncthreads();
#pragma unroll
        for (int l = 0; l < 2; l++) {
            const int ig = ci * 2 + l;
#pragma unroll
            for (int kz = 0; kz < 3; kz++) {
#pragma unroll
                for (int ky = 0; ky < 3; ky++) {
                    const float* wp = &wblk[ol * 432 + ig * 27 + kz * 9 + ky * 3];
                    u64 w0p = dupf(wp[0]), w1p = dupf(wp[1]), w2p = dupf(wp[2]);
                    const float* line = &s[((l * 6 + lh + kz) * 18 + lw + ky) * 34];
                    u64 prev = *(const u64*)&line[0];
#pragma unroll
                    for (int i = 0; i < 16; i++) {
                        u64 cur = *(const u64*)&line[2 * i + 2];
                        float2 pv = up(prev), cv = up(cur);
                        u64 mid = pk(pv.y, cv.x);
                        ffma2(acc2[i], w0p, prev);
                        ffma2(acc2[i], w1p, mid);
                        ffma2(acc2[i], w2p, cur);
                        prev = cur;
                    }
                }
            }
        }
    }
    const float bb = bd[oc];
    float* dst = &g_outconv[((size_t)(b * 128 + oc)) * NTOK + (h0 + lh) * 1024 + (w0 + lw) * 32];
#pragma unroll
    for (int i = 0; i < 16; i++) {
        float2 f = up(acc2[i]);
        *(float2*)&dst[2 * i] = make_float2(f.x + bb, f.y + bb);
    }
}

// ------------------------- K8: spatial + channel attention (packed CA) --------
__global__ __launch_bounds__(128) void k8_attn() {
    __shared__ float kps[2048];
    __shared__ float vp[2048];
    __shared__ float attT[32 * 34];   // transposed attn_CA: [e][d]
    __shared__ float qt[32 * 68];
    __shared__ float vca[32 * 68];
    __shared__ float sas[64 * 33];
    const int t = threadIdx.x;
    const int chunk = blockIdx.x;
    const int b = blockIdx.y;
    const int n0 = chunk * 64;
    const int tok = t >> 1, ph = t & 1, p0 = ph * 32;

    for (int h = 0; h < 4; h++) {
        const int bh = b * 4 + h;
        __syncthreads();
        for (int i = t; i < 2048; i += 128) {
            kps[i] = g_kps[bh * 2048 + i];
            vp[i] = g_vproj[bh * 2048 + i];
        }
        for (int i = t; i < 1024; i += 128) {
            int d = i >> 5, e = i & 31;
            attT[e * 34 + d] = g_attnCA[bh * 1024 + i];
        }
        for (int i = t; i < 2048; i += 128) {
            int dd = i >> 6, tt = i & 63;
            qt[dd * 68 + tt]  = g_qkvvT[((size_t)(b * 512 + h * 32 + dd)) * NTOK + n0 + tt];
            vca[dd * 68 + tt] = g_qkvvT[((size_t)(b * 512 + 256 + h * 32 + dd)) * NTOK + n0 + tt];
        }
        __syncthreads();

        u64 l2[16];
#pragma unroll
        for (int j = 0; j < 16; j++) l2[j] = 0ull;
        for (int d = 0; d < 32; d++) {
            u64 qd2 = dupf(qt[d * 68 + tok]);
            const u64* kk2 = (const u64*)&kps[d * 64 + p0];
#pragma unroll
            for (int j = 0; j < 16; j++) ffma2(l2[j], qd2, kk2[j]);
        }
        float l[32];
#pragma unroll
        for (int j = 0; j < 16; j++) { float2 f = up(l2[j]); l[2 * j] = f.x; l[2 * j + 1] = f.y; }
        float m = l[0];
#pragma unroll
        for (int j = 1; j < 32; j++) m = fmaxf(m, l[j]);
        m = fmaxf(m, __shfl_xor_sync(0xffffffffu, m, 1));
        float ssum = 0.f;
#pragma unroll
        for (int j = 0; j < 32; j++) { l[j] = expf(l[j] - m); ssum += l[j]; }
        ssum += __shfl_xor_sync(0xffffffffu, ssum, 1);
        const float inv = 1.f / ssum;
#pragma unroll
        for (int j = 0; j < 16; j++) l2[j] = pk(l[2 * j], l[2 * j + 1]);

        for (int d = 0; d < 32; d++) {
            const u64* vv2 = (const u64*)&vp[d * 64 + p0];
            u64 v2 = 0ull;
#pragma unroll
            for (int j = 0; j < 16; j++) ffma2(v2, l2[j], vv2[j]);
            float v = hadd(v2);
            v += __shfl_xor_sync(0xffffffffu, v, 1);
            if (ph == 0) sas[tok * 33 + d] = v * inv;
        }

        // channel attention, FFMA2-packed over d-pairs
        {
            u64 oacc[8];
#pragma unroll
            for (int j = 0; j < 8; j++) oacc[j] = 0ull;
#pragma unroll 4
            for (int e = 0; e < 32; e++) {
                u64 vd = dupf(vca[e * 68 + tok]);
                const u64* arow = (const u64*)&attT[e * 34 + ph * 16];
#pragma unroll
                for (int j = 0; j < 8; j++) ffma2(oacc[j], vd, arow[j]);
            }
            float2 f0 = up(oacc[0]), f1 = up(oacc[1]), f2 = up(oacc[2]), f3 = up(oacc[3]);
            float2 f4 = up(oacc[4]), f5 = up(oacc[5]), f6 = up(oacc[6]), f7 = up(oacc[7]);
            float4* dst = (float4*)&g_xCA[((size_t)(b * NTOK + n0 + tok)) * 128 + h * 32 + ph * 16];
            dst[0] = make_float4(f0.x, f0.y, f1.x, f1.y);
            dst[1] = make_float4(f2.x, f2.y, f3.x, f3.y);
            dst[2] = make_float4(f4.x, f4.y, f5.x, f5.y);
            dst[3] = make_float4(f6.x, f6.y, f7.x, f7.y);
        }
        __syncthreads();
        {
            const int q = n0 >> 7;
            const int cb = n0 & 127;
            for (int i = t; i < 2048; i += 128) {
                int dd = i >> 6, r = i & 63;
                g_SA[((size_t)(b * NTOK + dd * 1024 + h * 256 + q)) * 128 + cb + r] =
                    sas[r * 33 + dd];
            }
        }
    }
}

// ------------------------- K9: output GEMMs + combine (packed dot) ------------
extern __shared__ float dynsm[];
__global__ __launch_bounds__(256) void k9_final(const float* __restrict__ Wout,
                                                const float* __restrict__ bout,
                                                const float* __restrict__ Wout2,
                                                const float* __restrict__ bout2,
                                                const float* __restrict__ rate,
                                                const float* __restrict__ rate2,
                                                float* __restrict__ out) {
    float* Wc   = dynsm;            // 128*130
    float* bias = Wc + 128 * 130;   // 128
    float* sa   = bias + 128;       // 64*132
    float* ca   = sa + 64 * 132;    // 64*132
    float* cv   = ca + 64 * 132;    // 128*65
    const int t = threadIdx.x;
    const int b = blockIdx.y;
    const int n0 = blockIdx.x * 64;

    for (int i = t; i < 4096; i += 256) {
        int c = i >> 5, k4 = (i & 31) * 4;
        float4 v = (c < 64) ? *(const float4*)&Wout[c * 128 + k4]
                            : *(const float4*)&Wout2[(c - 64) * 128 + k4];
        Wc[c * 130 + k4 + 0] = v.x; Wc[c * 130 + k4 + 1] = v.y;
        Wc[c * 130 + k4 + 2] = v.z; Wc[c * 130 + k4 + 3] = v.w;
    }
    if (t < 128) bias[t] = (t < 64) ? bout[t] : bout2[t - 64];
    for (int i = t; i < 2048; i += 256) {
        int tt = i >> 5, k4 = (i & 31) * 4;
        *(float4*)&sa[tt * 132 + k4] = *(const float4*)&g_SA[((size_t)(b * NTOK + n0 + tt)) * 128 + k4];
        *(float4*)&ca[tt * 132 + k4] = *(const float4*)&g_xCA[((size_t)(b * NTOK + n0 + tt)) * 128 + k4];
    }
    for (int i = t; i < 2048; i += 256) {
        int c = i >> 4, tt4 = (i & 15) * 4;
        float4 v = *(const float4*)&g_outconv[((size_t)(b * 128 + c)) * NTOK + n0 + tt4];
        cv[c * 65 + tt4 + 0] = v.x; cv[c * 65 + tt4 + 1] = v.y;
        cv[c * 65 + tt4 + 2] = v.z; cv[c * 65 + tt4 + 3] = v.w;
    }
    __syncthreads();
    const float r1 = rate[0], r2 = rate2[0];
    const int tok = t >> 2, cb = t & 3;
    const float* sarow = &sa[tok * 132];
    const float* carow = &ca[tok * 132];
#pragma unroll
    for (int j = 0; j < 32; j++) {
        const int c = cb + j * 4;
        const float* row = (c < 64) ? sarow : carow;
        const float* wr = &Wc[c * 130];
        u64 a2 = 0ull;
#pragma unroll 8
        for (int k = 0; k < 128; k += 4) {
            ffma2(a2, *(const u64*)&row[k], *(const u64*)&wr[k]);
            ffma2(a2, *(const u64*)&row[k + 2], *(const u64*)&wr[k + 2]);
        }
        float acc = bias[c] + hadd(a2);
        out[((size_t)(b * NTOK + n0 + tok)) * 128 + c] = r1 * acc + r2 * cv[c * 65 + tok];
    }
}

// ------------------------- launch ---------------------------------------------
extern "C" void kernel_launch(void* const* d_in, const int* in_sizes, int n_in,
                              void* d_out, int out_size) {
    const float* x      = (const float*)d_in[0];
    const float* Wqkvv  = (const float*)d_in[1];
    const float* W_fc   = (const float*)d_in[2];
    const float* b_fc   = (const float*)d_in[3];
    const float* W_dep  = (const float*)d_in[4];
    const float* b_dep  = (const float*)d_in[5];
    const float* W_E    = (const float*)d_in[6];
    const float* b_E    = (const float*)d_in[7];
    const float* temp   = (const float*)d_in[8];
    const float* temp2  = (const float*)d_in[9];
    const float* rate   = (const float*)d_in[10];
    const float* rate2  = (const float*)d_in[11];
    const float* W_out  = (const float*)d_in[12];
    const float* b_out  = (const float*)d_in[13];
    const float* W_out2 = (const float*)d_in[14];
    const float* b_out2 = (const float*)d_in[15];
    float* out = (float*)d_out;

    const int k9_smem = (128 * 130 + 128 + 64 * 132 * 2 + 128 * 65) * 4;
    cudaFuncSetAttribute(k9_final, cudaFuncAttributeMaxDynamicSharedMemorySize, k9_smem);

    k1_qkvv<<<dim3(256, 8, 4), 256>>>(x, Wqkvv);
    k2_gram<<<dim3(64, 4, 4), 256>>>();
    k3_red<<<16, 256>>>(temp);
    k4_proj<<<dim3(16, 16, 2), 256>>>(W_E);
    k5_projred<<<16, 256>>>(b_E, temp2);
    k6_fc<<<dim3(32, 4, 4), 256>>>(W_fc, b_fc);
    k7_conv<<<dim3(16, 32, 4), 256>>>(W_dep, b_dep);
    k8_attn<<<dim3(512, 4), 128>>>();
    k9_final<<<dim3(512, 4), 256, k9_smem>>>(W_out, b_out, W_out2, b_out2, rate, rate2, out);
}

// round 11
// speedup vs baseline: 1.1942x; 1.1942x over previous
#include <cuda_runtime.h>
#include <math.h>

#define NTOK 32768
#define NB 4

typedef unsigned long long u64;

__device__ __forceinline__ u64 pk(float lo, float hi) {
    u64 r; asm("mov.b64 %0,{%1,%2};" : "=l"(r) : "f"(lo), "f"(hi)); return r;
}
__device__ __forceinline__ u64 dupf(float v) {
    u64 r; asm("mov.b64 %0,{%1,%1};" : "=l"(r) : "f"(v)); return r;
}
__device__ __forceinline__ float2 up(u64 v) {
    float2 f; asm("mov.b64 {%0,%1},%2;" : "=f"(f.x), "=f"(f.y) : "l"(v)); return f;
}
__device__ __forceinline__ void ffma2(u64& d, u64 a, u64 b) {
    asm("fma.rn.f32x2 %0,%1,%2,%0;" : "+l"(d) : "l"(a), "l"(b));
}
__device__ __forceinline__ float hadd(u64 v) { float2 f = up(v); return f.x + f.y; }

// ------------------------- scratch (__device__ globals) -------------------------
__device__ float g_qkvvT[(size_t)NB * 512 * NTOK];   // [b][j][n]  j: 0q 128k 256vCA 384vSA
__device__ float g_outconv[(size_t)NB * 128 * NTOK]; // [b][oc][n]
__device__ float g_SA[(size_t)NB * NTOK * 128];      // scrambled x_SA rows
__device__ float g_xCA[(size_t)NB * NTOK * 128];     // [b][n][c]
__device__ float g_gpart[16 * 64 * 1088];
__device__ float g_ppart[16 * 16 * 2 * 2048];
__device__ float g_nq[512];
__device__ float g_attnCA[16 * 1024];
__device__ float g_kps[16 * 2048];
__device__ float g_vproj[16 * 2048];
__device__ float g_Weff[128 * 459];                  // [oc][ch 0..16][27]; ch16 = b_fc field

// ---------------- K0: compose 1x1 conv into depthwise weights -----------------
// Weff[oc][ch][tap] = sum_ig Wdep[oc][ig][tap] * (ch<16 ? Wfc[ig][ch] : bfc[ig])
__global__ __launch_bounds__(256) void k0_weff(const float* __restrict__ Wfc,
                                               const float* __restrict__ bfc,
                                               const float* __restrict__ Wd) {
    const int oc = blockIdx.x;
    const int t = threadIdx.x;
    for (int idx = t; idx < 459; idx += 256) {
        const int ch = idx / 27, tap = idx - ch * 27;
        float s = 0.f;
#pragma unroll
        for (int ig = 0; ig < 16; ig++) {
            float wsrc = (ch < 16) ? Wfc[ig * 16 + ch] : bfc[ig];
            s += Wd[oc * 432 + ig * 27 + tap] * wsrc;
        }
        g_Weff[oc * 459 + idx] = s;
    }
}

// ------------------------- K1: qkvvT = Wq @ x  (R5/R9 version) ----------------
__global__ __launch_bounds__(256) void k1_qkvv(const float* __restrict__ x,
                                               const float* __restrict__ Wq) {
    __shared__ float xs[32 * 128];
    __shared__ u64 ws2[32 * 64];
    const int t = threadIdx.x;
    const int n0 = blockIdx.x * 128;
    const int j0 = blockIdx.y * 64;
    const int b  = blockIdx.z;
    const int nt = t & 31;
    const int jt = t >> 5;
    u64 acc0[8], acc1[8];
#pragma unroll
    for (int j = 0; j < 8; j++) { acc0[j] = 0ull; acc1[j] = 0ull; }

    for (int kc = 0; kc < 4; kc++) {
        const int k0 = kc * 32;
#pragma unroll
        for (int r = 0; r < 16; r++) {
            int e = t + r * 256;
            int kk = e >> 7, nl = e & 127;
            xs[e] = x[((size_t)(b * 128 + k0 + kk)) * NTOK + n0 + nl];
        }
#pragma unroll
        for (int r = 0; r < 8; r++) {
            int e = t + r * 256;
            int kk = e >> 6, j = e & 63;
            ws2[kk * 64 + j] = dupf(Wq[(j0 + j) * 128 + k0 + kk]);
        }
        __syncthreads();
#pragma unroll
        for (int kk = 0; kk < 32; kk++) {
            float4 xv = *(const float4*)&xs[kk * 128 + nt * 4];
            u64 x0 = pk(xv.x, xv.y), x1 = pk(xv.z, xv.w);
            const u64* wrow = &ws2[kk * 64 + jt * 8];
#pragma unroll
            for (int jj = 0; jj < 8; jj++) {
                u64 w = wrow[jj];
                ffma2(acc0[jj], x0, w);
                ffma2(acc1[jj], x1, w);
            }
        }
        __syncthreads();
    }
#pragma unroll
    for (int jj = 0; jj < 8; jj++) {
        float2 a0 = up(acc0[jj]), a1 = up(acc1[jj]);
        size_t rb = ((size_t)(b * 512 + j0 + jt * 8 + jj)) * NTOK + n0 + nt * 4;
        *(float4*)&g_qkvvT[rb] = make_float4(a0.x, a0.y, a1.x, a1.y);
    }
}

// ------------------------- K2: Gram partials + sq-sums (packed over tt) -------
__global__ __launch_bounds__(256) void k2_gram() {
    __shared__ float qs[32 * 66];
    __shared__ float ks[32 * 66];
    const int s = blockIdx.x;
    const int h = blockIdx.y, b = blockIdx.z;
    const int bh = b * 4 + h;
    const int t = threadIdx.x;
    const int d = t >> 3, e0 = (t & 7) * 4;
    u64 acc2[4] = {0ull, 0ull, 0ull, 0ull};
    u64 nacc2 = 0ull;
    for (int sub = 0; sub < 8; sub++) {
        const int n0 = s * 512 + sub * 64;
#pragma unroll
        for (int r = 0; r < 8; r++) {
            int e = t + r * 256;
            int dd = e >> 6, tt = e & 63;
            qs[dd * 66 + tt] = g_qkvvT[((size_t)(b * 512 + h * 32 + dd)) * NTOK + n0 + tt];
            ks[dd * 66 + tt] = g_qkvvT[((size_t)(b * 512 + 128 + h * 32 + dd)) * NTOK + n0 + tt];
        }
        __syncthreads();
#pragma unroll 8
        for (int tt = 0; tt < 64; tt += 2) {
            u64 qp = *(const u64*)&qs[d * 66 + tt];
#pragma unroll
            for (int j = 0; j < 4; j++)
                ffma2(acc2[j], qp, *(const u64*)&ks[(e0 + j) * 66 + tt]);
        }
        if (t < 32) {
#pragma unroll 8
            for (int tt = 0; tt < 64; tt += 2) {
                u64 v = *(const u64*)&qs[t * 66 + tt];
                ffma2(nacc2, v, v);
            }
        } else if (t < 64) {
#pragma unroll 8
            for (int tt = 0; tt < 64; tt += 2) {
                u64 v = *(const u64*)&ks[(t - 32) * 66 + tt];
                ffma2(nacc2, v, v);
            }
        }
        __syncthreads();
    }
    float* part = &g_gpart[(bh * 64 + s) * 1088];
#pragma unroll
    for (int j = 0; j < 4; j++) part[d * 32 + e0 + j] = hadd(acc2[j]);
    if (t < 64) part[1024 + t] = hadd(nacc2);
}

// ------------------------- K3: reduce Gram -> norms, attn_CA ------------------
__global__ __launch_bounds__(256) void k3_red(const float* __restrict__ temperature) {
    __shared__ float Gs[32 * 33];
    __shared__ float nqs[32], nks[32];
    const int bh = blockIdx.x;
    const int h = bh & 3;
    const int t = threadIdx.x;
    for (int i = t; i < 1024; i += 256) {
        float s = 0.f;
        for (int c = 0; c < 64; c++) s += g_gpart[(bh * 64 + c) * 1088 + i];
        Gs[(i >> 5) * 33 + (i & 31)] = s;
    }
    if (t < 64) {
        float s = 0.f;
        for (int c = 0; c < 64; c++) s += g_gpart[(bh * 64 + c) * 1088 + 1024 + t];
        float nv = fmaxf(sqrtf(s), 1e-12f);
        if (t < 32) { nqs[t] = nv; g_nq[bh * 32 + t] = nv; }
        else        { nks[t - 32] = nv; }
    }
    __syncthreads();
    if (t < 32) {
        const int d = t;
        const float temp = temperature[h];
        float v[32];
        float m = -3.4e38f;
        float inq = 1.f / nqs[d];
#pragma unroll
        for (int e = 0; e < 32; e++) {
            v[e] = Gs[d * 33 + e] * temp * inq / nks[e];
            m = fmaxf(m, v[e]);
        }
        float ssum = 0.f;
#pragma unroll
        for (int e = 0; e < 32; e++) { v[e] = expf(v[e] - m); ssum += v[e]; }
        float inv = 1.f / ssum;
#pragma unroll
        for (int e = 0; e < 32; e++) g_attnCA[bh * 1024 + d * 32 + e] = v[e] * inv;
    }
}

// ------------------------- K4: E/F projections (R5/R9 version) ----------------
__global__ __launch_bounds__(256) void k4_proj(const float* __restrict__ WE) {
    __shared__ float kt[32 * 66];
    __shared__ float vt[32 * 66];
    __shared__ float wt[64 * 66];
    const int chunk = blockIdx.x;  // 0..15
    const int bh = blockIdx.y;
    const int b = bh >> 2, h = bh & 3;
    const int t = threadIdx.x;
    const int p = t & 63;
    const int dbase = (t >> 6) * 8;
    u64 ak2[8], av2[8];
#pragma unroll
    for (int j = 0; j < 8; j++) { ak2[j] = 0ull; av2[j] = 0ull; }
    for (int sub = 0; sub < 32; sub++) {
        const int n0 = chunk * 2048 + sub * 64;
#pragma unroll
        for (int r = 0; r < 8; r++) {
            int e = t + r * 256;
            int dd = e >> 6, tt = e & 63;
            kt[dd * 66 + tt] = g_qkvvT[((size_t)(b * 512 + 128 + h * 32 + dd)) * NTOK + n0 + tt];
            vt[dd * 66 + tt] = g_qkvvT[((size_t)(b * 512 + 384 + h * 32 + dd)) * NTOK + n0 + tt];
        }
#pragma unroll
        for (int r = 0; r < 16; r++) {
            int e = t + r * 256;
            int pp = e >> 6, tt = e & 63;
            wt[pp * 66 + tt] = WE[(size_t)pp * NTOK + n0 + tt];
        }
        __syncthreads();
#pragma unroll 4
        for (int tt = 0; tt < 64; tt += 2) {
            u64 wp = *(const u64*)&wt[p * 66 + tt];
#pragma unroll
            for (int j = 0; j < 8; j++) {
                ffma2(ak2[j], *(const u64*)&kt[(dbase + j) * 66 + tt], wp);
                ffma2(av2[j], *(const u64*)&vt[(dbase + j) * 66 + tt], wp);
            }
        }
        __syncthreads();
    }
    float* pko = &g_ppart[((size_t)(bh * 16 + chunk) * 2) * 2048];
#pragma unroll
    for (int j = 0; j < 8; j++) {
        pko[(dbase + j) * 64 + p] = hadd(ak2[j]);
        pko[2048 + (dbase + j) * 64 + p] = hadd(av2[j]);
    }
}

// ------------------------- K5: reduce projections, fold scales ----------------
__global__ __launch_bounds__(256) void k5_projred(const float* __restrict__ bE,
                                                  const float* __restrict__ temp2) {
    const int bh = blockIdx.x;
    const int h = bh & 3;
    const int t = threadIdx.x;
    const float t2 = temp2[h];
    for (int idx = t; idx < 2048; idx += 256) {
        const int d = idx >> 6, p = idx & 63;
        float sk = 0.f, sv = 0.f;
        for (int c = 0; c < 16; c++) {
            const float* base = &g_ppart[((size_t)(bh * 16 + c) * 2) * 2048];
            sk += base[idx];
            sv += base[2048 + idx];
        }
        const float be = bE[p];
        g_kps[bh * 2048 + idx] = (sk + be) * t2 / g_nq[bh * 32 + d];
        g_vproj[bh * 2048 + idx] = sv + be;
    }
}

// ---------- K7: fused (1x1 ∘ grouped 3x3x3) conv straight from qkvvT ----------
__global__ __launch_bounds__(256) void k7_conv(const float* __restrict__ bd) {
    __shared__ float s[2 * 6 * 18 * 34];
    __shared__ float wblk[4 * 459];   // 4 ol x 17 ch x 27 taps
    const int t = threadIdx.x;
    const int tile = blockIdx.x;
    const int g = blockIdx.y;
    const int b = blockIdx.z;
    const int h0 = (tile >> 1) * 4;
    const int w0 = (tile & 1) * 16;
    for (int i = t; i < 1836; i += 256) {
        int ol = i / 459, rem = i - ol * 459;
        wblk[i] = g_Weff[(g * 4 + ol) * 459 + rem];
    }
    const int lw = t & 15, lh = (t >> 4) & 3, ol = t >> 6;
    const int oc = g * 4 + ol;
    u64 acc2[16];
#pragma unroll
    for (int j = 0; j < 16; j++) acc2[j] = 0ull;

    for (int ci = 0; ci < 9; ci++) {
        __syncthreads();
        if (t < 216) {
            const int l = t / 108, rem = t % 108;
            const int ch = ci * 2 + l;
            if (ch <= 16) {
                const int hh = rem / 18, ww = rem % 18;
                const int h_s = h0 - 1 + hh, w_s = w0 - 1 + ww;
                float* line = &s[((l * 6 + hh) * 18 + ww) * 34];
                if (h_s >= 0 && h_s < 32 && w_s >= 0 && w_s < 32) {
                    line[0] = 0.f;
                    line[33] = 0.f;
                    if (ch < 16) {
                        const float* src = &g_qkvvT[((size_t)(b * 512 + ch * 32 + g)) * NTOK +
                                                    h_s * 1024 + w_s * 32];
#pragma unroll
                        for (int k = 0; k < 8; k++) {
                            float4 v = *(const float4*)&src[k * 4];
                            line[1 + k * 4] = v.x; line[2 + k * 4] = v.y;
                            line[3 + k * 4] = v.z; line[4 + k * 4] = v.w;
                        }
                    } else {  // ch == 16: the b_fc bias field (ones inside the domain)
#pragma unroll
                        for (int k = 0; k < 32; k++) line[1 + k] = 1.f;
                    }
                } else {
#pragma unroll
                    for (int k = 0; k < 34; k++) line[k] = 0.f;
                }
            }
        }
        __syncthreads();
#pragma unroll
        for (int l = 0; l < 2; l++) {
            const int ch = ci * 2 + l;
            if (ch > 16) break;
#pragma unroll
            for (int kz = 0; kz < 3; kz++) {
#pragma unroll
                for (int ky = 0; ky < 3; ky++) {
                    const float* wp = &wblk[ol * 459 + ch * 27 + kz * 9 + ky * 3];
                    u64 w0p = dupf(wp[0]), w1p = dupf(wp[1]), w2p = dupf(wp[2]);
                    const float* line = &s[((l * 6 + lh + kz) * 18 + lw + ky) * 34];
                    u64 prev = *(const u64*)&line[0];
#pragma unroll
                    for (int i = 0; i < 16; i++) {
                        u64 cur = *(const u64*)&line[2 * i + 2];
                        float2 pv = up(prev), cv = up(cur);
                        u64 mid = pk(pv.y, cv.x);
                        ffma2(acc2[i], w0p, prev);
                        ffma2(acc2[i], w1p, mid);
                        ffma2(acc2[i], w2p, cur);
                        prev = cur;
                    }
                }
            }
        }
    }
    const float bb = bd[oc];
    float* dst = &g_outconv[((size_t)(b * 128 + oc)) * NTOK + (h0 + lh) * 1024 + (w0 + lw) * 32];
#pragma unroll
    for (int i = 0; i < 16; i++) {
        float2 f = up(acc2[i]);
        *(float2*)&dst[2 * i] = make_float2(f.x + bb, f.y + bb);
    }
}

// ------------------------- K8: spatial + channel attention (packed CA) --------
__global__ __launch_bounds__(128) void k8_attn() {
    __shared__ float kps[2048];
    __shared__ float vp[2048];
    __shared__ float attT[32 * 34];
    __shared__ float qt[32 * 68];
    __shared__ float vca[32 * 68];
    __shared__ float sas[64 * 33];
    const int t = threadIdx.x;
    const int chunk = blockIdx.x;
    const int b = blockIdx.y;
    const int n0 = chunk * 64;
    const int tok = t >> 1, ph = t & 1, p0 = ph * 32;

    for (int h = 0; h < 4; h++) {
        const int bh = b * 4 + h;
        __syncthreads();
        for (int i = t; i < 2048; i += 128) {
            kps[i] = g_kps[bh * 2048 + i];
            vp[i] = g_vproj[bh * 2048 + i];
        }
        for (int i = t; i < 1024; i += 128) {
            int d = i >> 5, e = i & 31;
            attT[e * 34 + d] = g_attnCA[bh * 1024 + i];
        }
        for (int i = t; i < 2048; i += 128) {
            int dd = i >> 6, tt = i & 63;
            qt[dd * 68 + tt]  = g_qkvvT[((size_t)(b * 512 + h * 32 + dd)) * NTOK + n0 + tt];
            vca[dd * 68 + tt] = g_qkvvT[((size_t)(b * 512 + 256 + h * 32 + dd)) * NTOK + n0 + tt];
        }
        __syncthreads();

        u64 l2[16];
#pragma unroll
        for (int j = 0; j < 16; j++) l2[j] = 0ull;
        for (int d = 0; d < 32; d++) {
            u64 qd2 = dupf(qt[d * 68 + tok]);
            const u64* kk2 = (const u64*)&kps[d * 64 + p0];
#pragma unroll
            for (int j = 0; j < 16; j++) ffma2(l2[j], qd2, kk2[j]);
        }
        float l[32];
#pragma unroll
        for (int j = 0; j < 16; j++) { float2 f = up(l2[j]); l[2 * j] = f.x; l[2 * j + 1] = f.y; }
        float m = l[0];
#pragma unroll
        for (int j = 1; j < 32; j++) m = fmaxf(m, l[j]);
        m = fmaxf(m, __shfl_xor_sync(0xffffffffu, m, 1));
        float ssum = 0.f;
#pragma unroll
        for (int j = 0; j < 32; j++) { l[j] = expf(l[j] - m); ssum += l[j]; }
        ssum += __shfl_xor_sync(0xffffffffu, ssum, 1);
        const float inv = 1.f / ssum;
#pragma unroll
        for (int j = 0; j < 16; j++) l2[j] = pk(l[2 * j], l[2 * j + 1]);

        for (int d = 0; d < 32; d++) {
            const u64* vv2 = (const u64*)&vp[d * 64 + p0];
            u64 v2 = 0ull;
#pragma unroll
            for (int j = 0; j < 16; j++) ffma2(v2, l2[j], vv2[j]);
            float v = hadd(v2);
            v += __shfl_xor_sync(0xffffffffu, v, 1);
            if (ph == 0) sas[tok * 33 + d] = v * inv;
        }

        {
            u64 oacc[8];
#pragma unroll
            for (int j = 0; j < 8; j++) oacc[j] = 0ull;
#pragma unroll 4
            for (int e = 0; e < 32; e++) {
                u64 vd = dupf(vca[e * 68 + tok]);
                const u64* arow = (const u64*)&attT[e * 34 + ph * 16];
#pragma unroll
                for (int j = 0; j < 8; j++) ffma2(oacc[j], vd, arow[j]);
            }
            float2 f0 = up(oacc[0]), f1 = up(oacc[1]), f2 = up(oacc[2]), f3 = up(oacc[3]);
            float2 f4 = up(oacc[4]), f5 = up(oacc[5]), f6 = up(oacc[6]), f7 = up(oacc[7]);
            float4* dst = (float4*)&g_xCA[((size_t)(b * NTOK + n0 + tok)) * 128 + h * 32 + ph * 16];
            dst[0] = make_float4(f0.x, f0.y, f1.x, f1.y);
            dst[1] = make_float4(f2.x, f2.y, f3.x, f3.y);
            dst[2] = make_float4(f4.x, f4.y, f5.x, f5.y);
            dst[3] = make_float4(f6.x, f6.y, f7.x, f7.y);
        }
        __syncthreads();
        {
            const int q = n0 >> 7;
            const int cb = n0 & 127;
            for (int i = t; i < 2048; i += 128) {
                int dd = i >> 6, r = i & 63;
                g_SA[((size_t)(b * NTOK + dd * 1024 + h * 256 + q)) * 128 + cb + r] =
                    sas[r * 33 + dd];
            }
        }
    }
}

// ------------------------- K9: output GEMMs + combine (packed dot) ------------
extern __shared__ float dynsm[];
__global__ __launch_bounds__(256) void k9_final(const float* __restrict__ Wout,
                                                const float* __restrict__ bout,
                                                const float* __restrict__ Wout2,
                                                const float* __restrict__ bout2,
                                                const float* __restrict__ rate,
                                                const float* __restrict__ rate2,
                                                float* __restrict__ out) {
    float* Wc   = dynsm;            // 128*130
    float* bias = Wc + 128 * 130;   // 128
    float* sa   = bias + 128;       // 64*132
    float* ca   = sa + 64 * 132;    // 64*132
    float* cv   = ca + 64 * 132;    // 128*65
    const int t = threadIdx.x;
    const int b = blockIdx.y;
    const int n0 = blockIdx.x * 64;

    for (int i = t; i < 4096; i += 256) {
        int c = i >> 5, k4 = (i & 31) * 4;
        float4 v = (c < 64) ? *(const float4*)&Wout[c * 128 + k4]
                            : *(const float4*)&Wout2[(c - 64) * 128 + k4];
        Wc[c * 130 + k4 + 0] = v.x; Wc[c * 130 + k4 + 1] = v.y;
        Wc[c * 130 + k4 + 2] = v.z; Wc[c * 130 + k4 + 3] = v.w;
    }
    if (t < 128) bias[t] = (t < 64) ? bout[t] : bout2[t - 64];
    for (int i = t; i < 2048; i += 256) {
        int tt = i >> 5, k4 = (i & 31) * 4;
        *(float4*)&sa[tt * 132 + k4] = *(const float4*)&g_SA[((size_t)(b * NTOK + n0 + tt)) * 128 + k4];
        *(float4*)&ca[tt * 132 + k4] = *(const float4*)&g_xCA[((size_t)(b * NTOK + n0 + tt)) * 128 + k4];
    }
    for (int i = t; i < 2048; i += 256) {
        int c = i >> 4, tt4 = (i & 15) * 4;
        float4 v = *(const float4*)&g_outconv[((size_t)(b * 128 + c)) * NTOK + n0 + tt4];
        cv[c * 65 + tt4 + 0] = v.x; cv[c * 65 + tt4 + 1] = v.y;
        cv[c * 65 + tt4 + 2] = v.z; cv[c * 65 + tt4 + 3] = v.w;
    }
    __syncthreads();
    const float r1 = rate[0], r2 = rate2[0];
    const int tok = t >> 2, cb = t & 3;
    const float* sarow = &sa[tok * 132];
    const float* carow = &ca[tok * 132];
#pragma unroll
    for (int j = 0; j < 32; j++) {
        const int c = cb + j * 4;
        const float* row = (c < 64) ? sarow : carow;
        const float* wr = &Wc[c * 130];
        u64 a2 = 0ull;
#pragma unroll 8
        for (int k = 0; k < 128; k += 4) {
            ffma2(a2, *(const u64*)&row[k], *(const u64*)&wr[k]);
            ffma2(a2, *(const u64*)&row[k + 2], *(const u64*)&wr[k + 2]);
        }
        float acc = bias[c] + hadd(a2);
        out[((size_t)(b * NTOK + n0 + tok)) * 128 + c] = r1 * acc + r2 * cv[c * 65 + tok];
    }
}

// ------------------------- launch ---------------------------------------------
extern "C" void kernel_launch(void* const* d_in, const int* in_sizes, int n_in,
                              void* d_out, int out_size) {
    const float* x      = (const float*)d_in[0];
    const float* Wqkvv  = (const float*)d_in[1];
    const float* W_fc   = (const float*)d_in[2];
    const float* b_fc   = (const float*)d_in[3];
    const float* W_dep  = (const float*)d_in[4];
    const float* b_dep  = (const float*)d_in[5];
    const float* W_E    = (const float*)d_in[6];
    const float* b_E    = (const float*)d_in[7];
    const float* temp   = (const float*)d_in[8];
    const float* temp2  = (const float*)d_in[9];
    const float* rate   = (const float*)d_in[10];
    const float* rate2  = (const float*)d_in[11];
    const float* W_out  = (const float*)d_in[12];
    const float* b_out  = (const float*)d_in[13];
    const float* W_out2 = (const float*)d_in[14];
    const float* b_out2 = (const float*)d_in[15];
    float* out = (float*)d_out;

    const int k9_smem = (128 * 130 + 128 + 64 * 132 * 2 + 128 * 65) * 4;
    cudaFuncSetAttribute(k9_final, cudaFuncAttributeMaxDynamicSharedMemorySize, k9_smem);

    k0_weff<<<128, 256>>>(W_fc, b_fc, W_dep);
    k1_qkvv<<<dim3(256, 8, 4), 256>>>(x, Wqkvv);
    k2_gram<<<dim3(64, 4, 4), 256>>>();
    k3_red<<<16, 256>>>(temp);
    k4_proj<<<dim3(16, 16), 256>>>(W_E);
    k5_projred<<<16, 256>>>(b_E, temp2);
    k7_conv<<<dim3(16, 32, 4), 256>>>(b_dep);
    k8_attn<<<dim3(512, 4), 128>>>();
    k9_final<<<dim3(512, 4), 256, k9_smem>>>(W_out, b_out, W_out2, b_out2, rate, rate2, out);
}